// round 3
// baseline (speedup 1.0000x reference)
#include <cuda_runtime.h>
#include <cstdint>

#define N_TOKENS 8192
#define D_MODEL  1024
#define D_FF     4096
#define N_EXPERTS 8

// ---------------- scratch (no allocation allowed) ----------------
__device__ int g_top1[N_TOKENS];
__device__ int g_perm[N_TOKENS];
__device__ int g_count[N_EXPERTS];
__device__ int g_offset[N_EXPERTS];
__device__ int g_cursor[N_EXPERTS];

// ---------------- init: zero counters every launch ----------------
__global__ void init_kernel() {
    int t = threadIdx.x;
    if (t < N_EXPERTS) { g_count[t] = 0; g_cursor[t] = 0; }
}

// ---------------- gate: one warp per token ----------------
__global__ void gate_kernel(const float* __restrict__ x,
                            const float* __restrict__ gw,
                            const float* __restrict__ gb) {
    int warp = (blockIdx.x * blockDim.x + threadIdx.x) >> 5;
    int lane = threadIdx.x & 31;
    if (warp >= N_TOKENS) return;
    const float* xr = x + (size_t)warp * D_MODEL;
    float acc[N_EXPERTS];
#pragma unroll
    for (int e = 0; e < N_EXPERTS; e++) acc[e] = 0.0f;
    for (int d = lane; d < D_MODEL; d += 32) {
        float xv = xr[d];
        const float* g = gw + (size_t)d * N_EXPERTS;
#pragma unroll
        for (int e = 0; e < N_EXPERTS; e++) acc[e] += xv * g[e];
    }
#pragma unroll
    for (int e = 0; e < N_EXPERTS; e++) {
#pragma unroll
        for (int o = 16; o > 0; o >>= 1)
            acc[e] += __shfl_down_sync(0xffffffffu, acc[e], o);
    }
    if (lane == 0) {
        int best = 0;
        float bv = acc[0] + gb[0];
#pragma unroll
        for (int e = 1; e < N_EXPERTS; e++) {
            float v = acc[e] + gb[e];
            if (v > bv) { bv = v; best = e; }   // strict > keeps first max, matches argmax
        }
        g_top1[warp] = best;
        atomicAdd(&g_count[best], 1);
    }
}

// ---------------- scan: 8 entries, one thread ----------------
__global__ void scan_kernel() {
    int off = 0;
    for (int e = 0; e < N_EXPERTS; e++) { g_offset[e] = off; off += g_count[e]; }
}

// ---------------- scatter tokens into per-expert segments ----------------
__global__ void scatter_kernel() {
    int n = blockIdx.x * blockDim.x + threadIdx.x;
    if (n >= N_TOKENS) return;
    int e = g_top1[n];
    int pos = g_offset[e] + atomicAdd(&g_cursor[e], 1);
    g_perm[pos] = n;
}

// ---------------- grouped fp32 GEMM ----------------
// grid: (D_FF/TN, ceil(N/TM), N_EXPERTS). Blocks past an expert's count exit.
#define TM 128
#define TN 128
#define TK 8

__global__ __launch_bounds__(256, 2)
void moe_gemm_kernel(const float* __restrict__ x,
                     const float* __restrict__ ew,
                     const float* __restrict__ eb,
                     float* __restrict__ out) {
    const int e = blockIdx.z;
    const int cnt = g_count[e];
    const int row0 = blockIdx.y * TM;
    if (row0 >= cnt) return;
    const int col0 = blockIdx.x * TN;
    const int off = g_offset[e];
    const float* __restrict__ W = ew + (size_t)e * D_MODEL * D_FF;

    __shared__ float As[TK][TM];
    __shared__ float Bs[TK][TN];
    __shared__ int   rows[TM];

    const int tid = threadIdx.x;
    if (tid < TM) {
        int r = row0 + tid;
        rows[tid] = (r < cnt) ? g_perm[off + r] : -1;
    }
    __syncthreads();

    // microtile mapping: 16 threads along N, 16 along M, each 8x8
    const int tx = tid & 15;
    const int ty = tid >> 4;

    float acc[8][8];
#pragma unroll
    for (int i = 0; i < 8; i++)
#pragma unroll
        for (int j = 0; j < 8; j++) acc[i][j] = 0.0f;

    // A load: 2 threads per row, float4 each (128 rows x 8 k)
    const int a_row  = tid >> 1;
    const int a_col4 = (tid & 1) * 4;
    const int a_tok  = rows[a_row];
    const float* a_src = (a_tok >= 0) ? (x + (size_t)a_tok * D_MODEL + a_col4) : nullptr;

    // B load: 32 threads per k-row, float4 each (8 k x 128 cols)
    const int b_row  = tid >> 5;
    const int b_col4 = (tid & 31) * 4;
    const float* b_src = W + (size_t)b_row * D_FF + col0 + b_col4;

    for (int k = 0; k < D_MODEL; k += TK) {
        float4 av = make_float4(0.f, 0.f, 0.f, 0.f);
        if (a_src) av = *(const float4*)(a_src + k);
        float4 bv = *(const float4*)(b_src + (size_t)k * D_FF);

        As[a_col4 + 0][a_row] = av.x;
        As[a_col4 + 1][a_row] = av.y;
        As[a_col4 + 2][a_row] = av.z;
        As[a_col4 + 3][a_row] = av.w;
        *(float4*)&Bs[b_row][b_col4] = bv;
        __syncthreads();

#pragma unroll
        for (int kk = 0; kk < TK; kk++) {
            float a[8], b[8];
#pragma unroll
            for (int i = 0; i < 8; i++) a[i] = As[kk][ty * 8 + i];
#pragma unroll
            for (int j = 0; j < 8; j++) b[j] = Bs[kk][tx * 8 + j];
#pragma unroll
            for (int i = 0; i < 8; i++)
#pragma unroll
                for (int j = 0; j < 8; j++)
                    acc[i][j] += a[i] * b[j];
        }
        __syncthreads();
    }

    // epilogue: add bias, scatter rows back to token order
    const float* brow = eb + (size_t)e * D_FF + col0 + tx * 8;
    float bias[8];
#pragma unroll
    for (int j = 0; j < 8; j++) bias[j] = brow[j];

#pragma unroll
    for (int i = 0; i < 8; i++) {
        int m = ty * 8 + i;
        int tok = rows[m];
        if (tok < 0) continue;
        float* orow = out + (size_t)tok * D_FF + col0 + tx * 8;
        float4 v0, v1;
        v0.x = acc[i][0] + bias[0]; v0.y = acc[i][1] + bias[1];
        v0.z = acc[i][2] + bias[2]; v0.w = acc[i][3] + bias[3];
        v1.x = acc[i][4] + bias[4]; v1.y = acc[i][5] + bias[5];
        v1.z = acc[i][6] + bias[6]; v1.w = acc[i][7] + bias[7];
        *(float4*)(orow + 0) = v0;
        *(float4*)(orow + 4) = v1;
    }
}

// ---------------- launch ----------------
extern "C" void kernel_launch(void* const* d_in, const int* in_sizes, int n_in,
                              void* d_out, int out_size) {
    const float* x  = (const float*)d_in[0];
    const float* gw = (const float*)d_in[1];
    const float* gb = (const float*)d_in[2];
    const float* ew = (const float*)d_in[3];
    const float* eb = (const float*)d_in[4];
    float* out = (float*)d_out;

    init_kernel<<<1, 32>>>();
    gate_kernel<<<(N_TOKENS * 32 + 255) / 256, 256>>>(x, gw, gb);
    scan_kernel<<<1, 1>>>();
    scatter_kernel<<<(N_TOKENS + 255) / 256, 256>>>();

    dim3 grid(D_FF / TN, (N_TOKENS + TM - 1) / TM, N_EXPERTS);
    moe_gemm_kernel<<<grid, 256>>>(x, ew, eb, out);
}

// round 6
// speedup vs baseline: 2.6242x; 2.6242x over previous
#include <cuda_runtime.h>
#include <cuda_bf16.h>
#include <cstdint>

#define N_TOKENS 8192
#define D_MODEL  1024
#define D_FF     4096
#define N_EXPERTS 8

// ================= scratch (static device arrays; no allocation) ==========
__device__ int g_top1[N_TOKENS];
__device__ int g_perm[N_TOKENS];
__device__ int g_count[N_EXPERTS];
__device__ int g_offset[N_EXPERTS];
__device__ int g_cursor[N_EXPERTS];

__device__ __nv_bfloat16 g_xhi[(size_t)N_TOKENS * D_MODEL];
__device__ __nv_bfloat16 g_xlo[(size_t)N_TOKENS * D_MODEL];
// W transposed to [e][f][k], K-major rows of 1024 bf16
__device__ __nv_bfloat16 g_whi[(size_t)N_EXPERTS * D_FF * D_MODEL];
__device__ __nv_bfloat16 g_wlo[(size_t)N_EXPERTS * D_FF * D_MODEL];

// ================= helpers =================
__device__ __forceinline__ uint32_t smem_u32(const void* p) {
    uint32_t a;
    asm("{ .reg .u64 t; cvta.to.shared.u64 t, %1; cvt.u32.u64 %0, t; }" : "=r"(a) : "l"(p));
    return a;
}
#define SWZ128(b) ((b) ^ (((b) >> 3) & 0x70))

__device__ __forceinline__ void cp16(uint32_t dst, const void* src, int src_sz) {
    asm volatile("cp.async.cg.shared.global [%0], [%1], 16, %2;"
                 :: "r"(dst), "l"(src), "r"(src_sz) : "memory");
}
__device__ __forceinline__ void cp_commit() {
    asm volatile("cp.async.commit_group;" ::: "memory");
}
template <int N>
__device__ __forceinline__ void cp_wait() {
    asm volatile("cp.async.wait_group %0;" :: "n"(N) : "memory");
}
__device__ __forceinline__ void ldsm4(uint32_t* r, uint32_t addr) {
    asm volatile("ldmatrix.sync.aligned.m8n8.x4.shared.b16 {%0,%1,%2,%3}, [%4];"
                 : "=r"(r[0]), "=r"(r[1]), "=r"(r[2]), "=r"(r[3]) : "r"(addr));
}
__device__ __forceinline__ void mma_bf16(float* d, const uint32_t* a,
                                         uint32_t b0, uint32_t b1) {
    asm volatile(
        "mma.sync.aligned.m16n8k16.row.col.f32.bf16.bf16.f32 "
        "{%0,%1,%2,%3}, {%4,%5,%6,%7}, {%8,%9}, {%0,%1,%2,%3};"
        : "+f"(d[0]), "+f"(d[1]), "+f"(d[2]), "+f"(d[3])
        : "r"(a[0]), "r"(a[1]), "r"(a[2]), "r"(a[3]), "r"(b0), "r"(b1));
}

// ================= routing kernels =================
__global__ void init_kernel() {
    int t = threadIdx.x;
    if (t < N_EXPERTS) { g_count[t] = 0; g_cursor[t] = 0; }
}

__global__ void gate_kernel(const float* __restrict__ x,
                            const float* __restrict__ gw,
                            const float* __restrict__ gb) {
    int warp = (blockIdx.x * blockDim.x + threadIdx.x) >> 5;
    int lane = threadIdx.x & 31;
    if (warp >= N_TOKENS) return;
    const float* xr = x + (size_t)warp * D_MODEL;
    float acc[N_EXPERTS];
#pragma unroll
    for (int e = 0; e < N_EXPERTS; e++) acc[e] = 0.0f;
    for (int d = lane; d < D_MODEL; d += 32) {
        float xv = xr[d];
        const float* g = gw + (size_t)d * N_EXPERTS;
#pragma unroll
        for (int e = 0; e < N_EXPERTS; e++) acc[e] += xv * g[e];
    }
#pragma unroll
    for (int e = 0; e < N_EXPERTS; e++)
#pragma unroll
        for (int o = 16; o > 0; o >>= 1)
            acc[e] += __shfl_down_sync(0xffffffffu, acc[e], o);
    if (lane == 0) {
        int best = 0;
        float bv = acc[0] + gb[0];
#pragma unroll
        for (int e = 1; e < N_EXPERTS; e++) {
            float v = acc[e] + gb[e];
            if (v > bv) { bv = v; best = e; }
        }
        g_top1[warp] = best;
        atomicAdd(&g_count[best], 1);
    }
}

__global__ void scan_kernel() {
    int off = 0;
    for (int e = 0; e < N_EXPERTS; e++) { g_offset[e] = off; off += g_count[e]; }
}

__global__ void scatter_kernel() {
    int n = blockIdx.x * blockDim.x + threadIdx.x;
    if (n >= N_TOKENS) return;
    int e = g_top1[n];
    int pos = g_offset[e] + atomicAdd(&g_cursor[e], 1);
    g_perm[pos] = n;
}

// ================= conversion pre-passes =================
__device__ __forceinline__ void split_bf16(float v, __nv_bfloat16& h, __nv_bfloat16& l) {
    h = __float2bfloat16(v);
    l = __float2bfloat16(v - __bfloat162float(h));
}

__global__ void convert_x_kernel(const float* __restrict__ x) {
    size_t i = (size_t)blockIdx.x * blockDim.x + threadIdx.x;  // float4 index
    float4 v = ((const float4*)x)[i];
    __nv_bfloat16 h0, h1, h2, h3, l0, l1, l2, l3;
    split_bf16(v.x, h0, l0); split_bf16(v.y, h1, l1);
    split_bf16(v.z, h2, l2); split_bf16(v.w, h3, l3);
    __nv_bfloat162 hh0 = __halves2bfloat162(h0, h1), hh1 = __halves2bfloat162(h2, h3);
    __nv_bfloat162 ll0 = __halves2bfloat162(l0, l1), ll1 = __halves2bfloat162(l2, l3);
    uint2 hp, lp;
    hp.x = *(uint32_t*)&hh0; hp.y = *(uint32_t*)&hh1;
    lp.x = *(uint32_t*)&ll0; lp.y = *(uint32_t*)&ll1;
    ((uint2*)g_xhi)[i] = hp;
    ((uint2*)g_xlo)[i] = lp;
}

// transpose W[e][k][f] -> W_t[e][f][k], 64x64 tiles
__global__ __launch_bounds__(256) void convert_w_kernel(const float* __restrict__ ew) {
    __shared__ float t[64][65];
    const int e = blockIdx.z;
    const int k0 = blockIdx.y * 64;
    const int f0 = blockIdx.x * 64;
    const float* W = ew + (size_t)e * D_MODEL * D_FF;
    const int tid = threadIdx.x;
#pragma unroll
    for (int p = 0; p < 16; p++) {
        int idx = p * 256 + tid;
        int r = idx >> 6, c = idx & 63;
        t[r][c] = W[(size_t)(k0 + r) * D_FF + f0 + c];
    }
    __syncthreads();
#pragma unroll
    for (int p = 0; p < 8; p++) {
        int idx = p * 256 + tid;
        int fr = idx >> 5, kc = (idx & 31) * 2;
        float v0 = t[kc][fr], v1 = t[kc + 1][fr];
        __nv_bfloat16 h0, h1, l0, l1;
        split_bf16(v0, h0, l0); split_bf16(v1, h1, l1);
        __nv_bfloat162 hh = __halves2bfloat162(h0, h1);
        __nv_bfloat162 ll = __halves2bfloat162(l0, l1);
        size_t o = ((size_t)e * D_FF + f0 + fr) * D_MODEL + k0 + kc;
        *(uint32_t*)(g_whi + o) = *(uint32_t*)&hh;
        *(uint32_t*)(g_wlo + o) = *(uint32_t*)&ll;
    }
}

// ================= mma.sync grouped GEMM (sm_103-safe, no tcgen05) ========
// tile: M=128 tokens x N=128 ff cols, K chunks of 64 bf16, double-buffered.
#define KC 64
#define NCHUNK (D_MODEL / KC)        // 16
#define MATB 16384                   // 128 rows * 128B (one bf16 matrix chunk)
#define BUFB (4 * MATB)              // A_hi, A_lo, B_hi, B_lo
#define SMEM_DYN (2 * BUFB)          // 128 KB

__global__ __launch_bounds__(256, 1)
void moe_hmma_kernel(const float* __restrict__ eb, float* __restrict__ out) {
    extern __shared__ char smem[];
    __shared__ int rows_s[128];

    const int e = blockIdx.z;
    const int cnt = g_count[e];
    const int row0 = blockIdx.y * 128;
    if (row0 >= cnt) return;
    const int col0 = blockIdx.x * 128;
    const int off = g_offset[e];

    const int tid = threadIdx.x;
    const int wid = tid >> 5;
    const int lane = tid & 31;
    const uint32_t sdyn = smem_u32(smem);

    if (tid < 128) {
        int r = row0 + tid;
        rows_s[tid] = (r < cnt) ? g_perm[off + r] : -1;
    }
    __syncthreads();

    // ---------- cp.async per-thread load plan (4 segments per matrix) ------
    // idx = p*256 + tid; smem row = idx>>3 (0..127); seg = idx&7 (16B units)
    size_t a_off[4]; int a_sz[4]; size_t b_off[4]; uint32_t dsw[4];
#pragma unroll
    for (int p = 0; p < 4; p++) {
        int idx = p * 256 + tid;
        int r = idx >> 3, seg = idx & 7;
        int tok = rows_s[r];
        a_sz[p]  = (tok >= 0) ? 16 : 0;
        a_off[p] = (size_t)(tok >= 0 ? tok : 0) * D_MODEL + seg * 8;
        b_off[p] = ((size_t)e * D_FF + col0 + r) * D_MODEL + seg * 8;
        dsw[p]   = SWZ128((uint32_t)(r * 128 + seg * 16));
    }

#define ISSUE(cc, buf)                                                     \
    {                                                                      \
        const uint32_t b0_ = sdyn + (buf) * BUFB;                          \
        const int ke_ = (cc) * KC;                                         \
        _Pragma("unroll")                                                  \
        for (int p = 0; p < 4; p++) {                                      \
            cp16(b0_ + dsw[p],            g_xhi + a_off[p] + ke_, a_sz[p]);\
            cp16(b0_ + MATB + dsw[p],     g_xlo + a_off[p] + ke_, a_sz[p]);\
            cp16(b0_ + 2*MATB + dsw[p],   g_whi + b_off[p] + ke_, 16);     \
            cp16(b0_ + 3*MATB + dsw[p],   g_wlo + b_off[p] + ke_, 16);     \
        }                                                                  \
        cp_commit();                                                       \
    }

    // ---------- warp tiling: 2 (M) x 4 (N) warps, each 64x32 ---------------
    const int wm = wid & 1;
    const int wn = wid >> 1;
    const int mi = lane >> 3, r8 = lane & 7;
    // A ldmatrix: matrix j: j&1 -> m+8, j>>1 -> k+8
    const int am = (mi & 1) * 8 + r8;          // local m row for this thread's addr
    const int ak = (mi >> 1) * 8;              // k element offset
    // B ldmatrix: matrix j: j>>1 -> n+8, j&1 -> k+8
    const int bn = (mi >> 1) * 8 + r8;
    const int bk = (mi & 1) * 8;

    uint32_t a_rowb[4], a_msk[4];              // per m16 tile
#pragma unroll
    for (int mt = 0; mt < 4; mt++) {
        int m = wm * 64 + mt * 16 + am;
        a_rowb[mt] = (uint32_t)m * 128;
        a_msk[mt]  = (uint32_t)(m & 7) << 4;
    }
    uint32_t b_rowb[2], b_msk[2];              // per n16 ldmatrix group
#pragma unroll
    for (int q = 0; q < 2; q++) {
        int n = wn * 32 + q * 16 + bn;
        b_rowb[q] = (uint32_t)n * 128;
        b_msk[q]  = (uint32_t)(n & 7) << 4;
    }

    float acc[4][4][4];
#pragma unroll
    for (int i = 0; i < 4; i++)
#pragma unroll
        for (int j = 0; j < 4; j++)
#pragma unroll
            for (int k = 0; k < 4; k++) acc[i][j][k] = 0.0f;

    ISSUE(0, 0);
    ISSUE(1, 1);

    for (int c = 0; c < NCHUNK; c++) {
        if (c < NCHUNK - 1) cp_wait<1>(); else cp_wait<0>();
        __syncthreads();

        const int buf = c & 1;
        const uint32_t Ah = sdyn + buf * BUFB;
        const uint32_t Al = Ah + MATB;
        const uint32_t Bh = Ah + 2 * MATB;
        const uint32_t Bl = Ah + 3 * MATB;

#pragma unroll
        for (int ks = 0; ks < 4; ks++) {
            uint32_t ahf[4][4], alf[4][4], bhf[2][4], blf[2][4];
            const uint32_t akb = (uint32_t)(ks * 32 + ak * 2);
            const uint32_t bkb = (uint32_t)(ks * 32 + bk * 2);
#pragma unroll
            for (int mt = 0; mt < 4; mt++) {
                uint32_t o = a_rowb[mt] + (akb ^ a_msk[mt]);
                ldsm4(ahf[mt], Ah + o);
                ldsm4(alf[mt], Al + o);
            }
#pragma unroll
            for (int q = 0; q < 2; q++) {
                uint32_t o = b_rowb[q] + (bkb ^ b_msk[q]);
                ldsm4(bhf[q], Bh + o);
                ldsm4(blf[q], Bl + o);
            }
#pragma unroll
            for (int mt = 0; mt < 4; mt++) {
#pragma unroll
                for (int nt = 0; nt < 4; nt++) {
                    const int q = nt >> 1, s = (nt & 1) * 2;
                    mma_bf16(acc[mt][nt], ahf[mt], bhf[q][s], bhf[q][s + 1]);
                    mma_bf16(acc[mt][nt], ahf[mt], blf[q][s], blf[q][s + 1]);
                    mma_bf16(acc[mt][nt], alf[mt], bhf[q][s], bhf[q][s + 1]);
                }
            }
        }
        __syncthreads();
        if (c + 2 < NCHUNK) ISSUE(c + 2, buf);
    }
#undef ISSUE

    // ---------- epilogue: bias + scatter to token rows ---------------------
    const int l4 = lane >> 2;
    const int l2 = (lane & 3) * 2;
#pragma unroll
    for (int nt = 0; nt < 4; nt++) {
        const int col = col0 + wn * 32 + nt * 8 + l2;
        const float2 bv = *(const float2*)(eb + (size_t)e * D_FF + col);
#pragma unroll
        for (int mt = 0; mt < 4; mt++) {
            const int mA = wm * 64 + mt * 16 + l4;
            const int tokA = rows_s[mA];
            const int tokB = rows_s[mA + 8];
            if (tokA >= 0) {
                float2 v;
                v.x = acc[mt][nt][0] + bv.x;
                v.y = acc[mt][nt][1] + bv.y;
                *(float2*)(out + (size_t)tokA * D_FF + col) = v;
            }
            if (tokB >= 0) {
                float2 v;
                v.x = acc[mt][nt][2] + bv.x;
                v.y = acc[mt][nt][3] + bv.y;
                *(float2*)(out + (size_t)tokB * D_FF + col) = v;
            }
        }
    }
}

// ================= launch =================
extern "C" void kernel_launch(void* const* d_in, const int* in_sizes, int n_in,
                              void* d_out, int out_size) {
    const float* x  = (const float*)d_in[0];
    const float* gw = (const float*)d_in[1];
    const float* gb = (const float*)d_in[2];
    const float* ew = (const float*)d_in[3];
    const float* eb = (const float*)d_in[4];
    float* out = (float*)d_out;

    cudaFuncSetAttribute(moe_hmma_kernel, cudaFuncAttributeMaxDynamicSharedMemorySize, SMEM_DYN);

    init_kernel<<<1, 32>>>();
    gate_kernel<<<(N_TOKENS * 32 + 255) / 256, 256>>>(x, gw, gb);
    scan_kernel<<<1, 1>>>();
    scatter_kernel<<<(N_TOKENS + 255) / 256, 256>>>();

    convert_x_kernel<<<(N_TOKENS * D_MODEL / 4) / 256, 256>>>(x);
    dim3 wgrid(D_FF / 64, D_MODEL / 64, N_EXPERTS);
    convert_w_kernel<<<wgrid, 256>>>(ew);

    // x = N-tile fastest so concurrent CTAs share the A slab in L2
    dim3 grid(D_FF / 128, (N_TOKENS + 127) / 128, N_EXPERTS);
    moe_hmma_kernel<<<grid, 256, SMEM_DYN>>>(eb, out);
}

// round 10
// speedup vs baseline: 5.5134x; 2.1009x over previous
#include <cuda_runtime.h>
#include <cuda_fp16.h>
#include <cstdint>

#define N_TOKENS 8192
#define D_MODEL  1024
#define D_FF     4096
#define N_EXPERTS 8

// ================= scratch (static device arrays; no allocation) ==========
__device__ int g_top1[N_TOKENS];
__device__ int g_perm[N_TOKENS];
__device__ int g_count[N_EXPERTS];
__device__ int g_offset[N_EXPERTS];
__device__ int g_cursor[N_EXPERTS];

__device__ __half g_xh[(size_t)N_TOKENS * D_MODEL];
// W transposed to [e][f][k], K-major rows of 1024 fp16
__device__ __half g_wh[(size_t)N_EXPERTS * D_FF * D_MODEL];

// ================= helpers =================
__device__ __forceinline__ uint32_t smem_u32(const void* p) {
    uint32_t a;
    asm("{ .reg .u64 t; cvta.to.shared.u64 t, %1; cvt.u32.u64 %0, t; }" : "=r"(a) : "l"(p));
    return a;
}
#define SWZ128(b) ((b) ^ (((b) >> 3) & 0x70))

__device__ __forceinline__ void cp16(uint32_t dst, const void* src, int src_sz) {
    asm volatile("cp.async.cg.shared.global [%0], [%1], 16, %2;"
                 :: "r"(dst), "l"(src), "r"(src_sz) : "memory");
}
__device__ __forceinline__ void cp_commit() {
    asm volatile("cp.async.commit_group;" ::: "memory");
}
template <int N>
__device__ __forceinline__ void cp_wait() {
    asm volatile("cp.async.wait_group %0;" :: "n"(N) : "memory");
}
__device__ __forceinline__ void ldsm4(uint32_t* r, uint32_t addr) {
    asm volatile("ldmatrix.sync.aligned.m8n8.x4.shared.b16 {%0,%1,%2,%3}, [%4];"
                 : "=r"(r[0]), "=r"(r[1]), "=r"(r[2]), "=r"(r[3]) : "r"(addr));
}
__device__ __forceinline__ void mma_f16(float* d, const uint32_t* a,
                                        uint32_t b0, uint32_t b1) {
    asm volatile(
        "mma.sync.aligned.m16n8k16.row.col.f32.f16.f16.f32 "
        "{%0,%1,%2,%3}, {%4,%5,%6,%7}, {%8,%9}, {%0,%1,%2,%3};"
        : "+f"(d[0]), "+f"(d[1]), "+f"(d[2]), "+f"(d[3])
        : "r"(a[0]), "r"(a[1]), "r"(a[2]), "r"(a[3]), "r"(b0), "r"(b1));
}

// ================= routing kernels =================
__global__ void init_kernel() {
    int t = threadIdx.x;
    if (t < N_EXPERTS) { g_count[t] = 0; g_cursor[t] = 0; }
}

__global__ void gate_kernel(const float* __restrict__ x,
                            const float* __restrict__ gw,
                            const float* __restrict__ gb) {
    int warp = (blockIdx.x * blockDim.x + threadIdx.x) >> 5;
    int lane = threadIdx.x & 31;
    if (warp >= N_TOKENS) return;
    const float* xr = x + (size_t)warp * D_MODEL;
    float acc[N_EXPERTS];
#pragma unroll
    for (int e = 0; e < N_EXPERTS; e++) acc[e] = 0.0f;
    for (int d = lane; d < D_MODEL; d += 32) {
        float xv = xr[d];
        const float* g = gw + (size_t)d * N_EXPERTS;
#pragma unroll
        for (int e = 0; e < N_EXPERTS; e++) acc[e] += xv * g[e];
    }
#pragma unroll
    for (int e = 0; e < N_EXPERTS; e++)
#pragma unroll
        for (int o = 16; o > 0; o >>= 1)
            acc[e] += __shfl_down_sync(0xffffffffu, acc[e], o);
    if (lane == 0) {
        int best = 0;
        float bv = acc[0] + gb[0];
#pragma unroll
        for (int e = 1; e < N_EXPERTS; e++) {
            float v = acc[e] + gb[e];
            if (v > bv) { bv = v; best = e; }
        }
        g_top1[warp] = best;
        atomicAdd(&g_count[best], 1);
    }
}

__global__ void scan_kernel() {
    int off = 0;
    for (int e = 0; e < N_EXPERTS; e++) { g_offset[e] = off; off += g_count[e]; }
}

__global__ void scatter_kernel() {
    int n = blockIdx.x * blockDim.x + threadIdx.x;
    if (n >= N_TOKENS) return;
    int e = g_top1[n];
    int pos = g_offset[e] + atomicAdd(&g_cursor[e], 1);
    g_perm[pos] = n;
}

// ================= conversion pre-passes =================
__global__ void convert_x_kernel(const float* __restrict__ x) {
    size_t i = (size_t)blockIdx.x * blockDim.x + threadIdx.x;  // float4 index
    float4 v = ((const float4*)x)[i];
    __half2 h0 = __floats2half2_rn(v.x, v.y);
    __half2 h1 = __floats2half2_rn(v.z, v.w);
    uint2 p;
    p.x = *(uint32_t*)&h0; p.y = *(uint32_t*)&h1;
    ((uint2*)g_xh)[i] = p;
}

// transpose W[e][k][f] -> W_t[e][f][k], 64x64 tiles
__global__ __launch_bounds__(256) void convert_w_kernel(const float* __restrict__ ew) {
    __shared__ float t[64][65];
    const int e = blockIdx.z;
    const int k0 = blockIdx.y * 64;
    const int f0 = blockIdx.x * 64;
    const float* W = ew + (size_t)e * D_MODEL * D_FF;
    const int tid = threadIdx.x;
#pragma unroll
    for (int p = 0; p < 16; p++) {
        int idx = p * 256 + tid;
        int r = idx >> 6, c = idx & 63;
        t[r][c] = W[(size_t)(k0 + r) * D_FF + f0 + c];
    }
    __syncthreads();
#pragma unroll
    for (int p = 0; p < 8; p++) {
        int idx = p * 256 + tid;
        int fr = idx >> 5, kc = (idx & 31) * 2;
        __half2 h = __floats2half2_rn(t[kc][fr], t[kc + 1][fr]);
        size_t o = ((size_t)e * D_FF + f0 + fr) * D_MODEL + k0 + kc;
        *(uint32_t*)(g_wh + o) = *(uint32_t*)&h;
    }
}

// ================= single-pass fp16 mma.sync grouped GEMM =================
// CTA: 128 threads (4 warps, 2x2), tile M=128 x N=128, warp tile 64x64.
// K chunks of 64 fp16 (one 128B SW128 row), 3-stage cp.async pipeline.
#define KC 64
#define NCHUNK (D_MODEL / KC)        // 16
#define MATB 16384                   // 128 rows * 128B
#define BUFB (2 * MATB)              // A, B
#define STAGES 3
#define SMEM_DYN (STAGES * BUFB)     // 96 KB

__global__ __launch_bounds__(128, 2)
void moe_hmma_kernel(const float* __restrict__ eb, float* __restrict__ out) {
    extern __shared__ char smem[];
    __shared__ int rows_s[128];

    const int e = blockIdx.z;
    const int cnt = g_count[e];
    const int row0 = blockIdx.y * 128;
    if (row0 >= cnt) return;
    const int col0 = blockIdx.x * 128;
    const int off = g_offset[e];

    const int tid = threadIdx.x;
    const int wid = tid >> 5;
    const int lane = tid & 31;
    const uint32_t sdyn = smem_u32(smem);

    {
        int r = row0 + tid;
        rows_s[tid] = (r < cnt) ? g_perm[off + r] : -1;
    }
    __syncthreads();

    const uint32_t wbase = ((uint32_t)e * D_FF + (uint32_t)col0) * D_MODEL;

    // cp.async: 8 (row, seg) pairs per thread per matrix
#define ISSUE(cc)                                                           \
    {                                                                       \
        const uint32_t b0_ = sdyn + ((cc) % STAGES) * BUFB;                 \
        const uint32_t ke_ = (uint32_t)(cc) * KC;                           \
        _Pragma("unroll")                                                   \
        for (int p = 0; p < 8; p++) {                                       \
            const int idx = p * 128 + tid;                                  \
            const int r = idx >> 3, seg = idx & 7;                          \
            const uint32_t d = SWZ128((uint32_t)(r * 128 + seg * 16));      \
            const int tok = rows_s[r];                                      \
            cp16(b0_ + d,                                                   \
                 g_xh + ((size_t)(tok < 0 ? 0 : tok) * D_MODEL + seg * 8 + ke_), \
                 tok < 0 ? 0 : 16);                                         \
            cp16(b0_ + MATB + d,                                            \
                 g_wh + ((size_t)wbase + (uint32_t)r * D_MODEL + seg * 8 + ke_), \
                 16);                                                       \
        }                                                                   \
        cp_commit();                                                        \
    }

    // ---------- warp tiling: 2 (M) x 2 (N) warps, each 64x64 ---------------
    const int wm = wid & 1;
    const int wn = wid >> 1;
    const int mi = lane >> 3, r8 = lane & 7;
    const int am = (mi & 1) * 8 + r8;          // A: j&1 -> m+8, j>>1 -> k+8
    const int ak = (mi >> 1) * 8;
    const int bn = (mi >> 1) * 8 + r8;         // B: j>>1 -> n+8, j&1 -> k+8
    const int bk = (mi & 1) * 8;

    uint32_t a_rowb[4], a_msk[4];              // 4 m16 tiles
#pragma unroll
    for (int mt = 0; mt < 4; mt++) {
        int m = wm * 64 + mt * 16 + am;
        a_rowb[mt] = (uint32_t)m * 128;
        a_msk[mt]  = (uint32_t)(m & 7) << 4;
    }
    uint32_t b_rowb[4], b_msk[4];              // 4 n16 ldmatrix groups
#pragma unroll
    for (int q = 0; q < 4; q++) {
        int n = wn * 64 + q * 16 + bn;
        b_rowb[q] = (uint32_t)n * 128;
        b_msk[q]  = (uint32_t)(n & 7) << 4;
    }

    float acc[4][8][4];
#pragma unroll
    for (int i = 0; i < 4; i++)
#pragma unroll
        for (int j = 0; j < 8; j++)
#pragma unroll
            for (int k = 0; k < 4; k++) acc[i][j][k] = 0.0f;

    ISSUE(0); ISSUE(1); ISSUE(2);

    for (int c = 0; c < NCHUNK; c++) {
        cp_wait<STAGES - 1>();
        __syncthreads();

        const uint32_t Ab = sdyn + (c % STAGES) * BUFB;
        const uint32_t Bb = Ab + MATB;

#pragma unroll
        for (int ks = 0; ks < 4; ks++) {
            uint32_t af[4][4], bf[4][4];
            const uint32_t akb = (uint32_t)(ks * 32 + ak * 2);
            const uint32_t bkb = (uint32_t)(ks * 32 + bk * 2);
#pragma unroll
            for (int mt = 0; mt < 4; mt++)
                ldsm4(af[mt], Ab + a_rowb[mt] + (akb ^ a_msk[mt]));
#pragma unroll
            for (int q = 0; q < 4; q++)
                ldsm4(bf[q], Bb + b_rowb[q] + (bkb ^ b_msk[q]));
#pragma unroll
            for (int mt = 0; mt < 4; mt++)
#pragma unroll
                for (int nt = 0; nt < 8; nt++) {
                    const int q = nt >> 1, s = (nt & 1) * 2;
                    mma_f16(acc[mt][nt], af[mt], bf[q][s], bf[q][s + 1]);
                }
        }
        __syncthreads();
        if (c + STAGES < NCHUNK) { ISSUE(c + STAGES); } else { cp_commit(); }
    }
#undef ISSUE

    // ---------- epilogue: bias + scatter to token rows ---------------------
    const int l4 = lane >> 2;
    const int l2 = (lane & 3) * 2;
#pragma unroll
    for (int nt = 0; nt < 8; nt++) {
        const int col = col0 + wn * 64 + nt * 8 + l2;
        const float2 bv = *(const float2*)(eb + (size_t)e * D_FF + col);
#pragma unroll
        for (int mt = 0; mt < 4; mt++) {
            const int mA = wm * 64 + mt * 16 + l4;
            const int tokA = rows_s[mA];
            const int tokB = rows_s[mA + 8];
            if (tokA >= 0) {
                float2 v;
                v.x = acc[mt][nt][0] + bv.x;
                v.y = acc[mt][nt][1] + bv.y;
                *(float2*)(out + (size_t)tokA * D_FF + col) = v;
            }
            if (tokB >= 0) {
                float2 v;
                v.x = acc[mt][nt][2] + bv.x;
                v.y = acc[mt][nt][3] + bv.y;
                *(float2*)(out + (size_t)tokB * D_FF + col) = v;
            }
        }
    }
}

// ================= launch =================
extern "C" void kernel_launch(void* const* d_in, const int* in_sizes, int n_in,
                              void* d_out, int out_size) {
    const float* x  = (const float*)d_in[0];
    const float* gw = (const float*)d_in[1];
    const float* gb = (const float*)d_in[2];
    const float* ew = (const float*)d_in[3];
    const float* eb = (const float*)d_in[4];
    float* out = (float*)d_out;

    cudaFuncSetAttribute(moe_hmma_kernel, cudaFuncAttributeMaxDynamicSharedMemorySize, SMEM_DYN);

    init_kernel<<<1, 32>>>();
    gate_kernel<<<(N_TOKENS * 32 + 255) / 256, 256>>>(x, gw, gb);
    scan_kernel<<<1, 1>>>();
    scatter_kernel<<<(N_TOKENS + 255) / 256, 256>>>();

    convert_x_kernel<<<(N_TOKENS * D_MODEL / 4) / 256, 256>>>(x);
    dim3 wgrid(D_FF / 64, D_MODEL / 64, N_EXPERTS);
    convert_w_kernel<<<wgrid, 256>>>(ew);

    // x = N-tile fastest so concurrent CTAs share the A slab in L2
    dim3 grid(D_FF / 128, (N_TOKENS + 127) / 128, N_EXPERTS);
    moe_hmma_kernel<<<grid, 128, SMEM_DYN>>>(eb, out);
}

// round 17
// speedup vs baseline: 5.5623x; 1.0089x over previous
#include <cuda_runtime.h>
#include <cuda_fp16.h>
#include <cstdint>

#define N_TOKENS 8192
#define D_MODEL  1024
#define D_FF     4096
#define N_EXPERTS 8

// ================= scratch (static device arrays; no allocation) ==========
__device__ int g_top1[N_TOKENS];
__device__ int g_perm[N_TOKENS];
__device__ int g_count[N_EXPERTS];
__device__ int g_offset[N_EXPERTS];
__device__ int g_cursor[N_EXPERTS];

__device__ __half g_xh[(size_t)N_TOKENS * D_MODEL];
// W transposed to [e][f][k], K-major rows of 1024 fp16
__device__ __half g_wh[(size_t)N_EXPERTS * D_FF * D_MODEL];

// ================= helpers =================
__device__ __forceinline__ uint32_t smem_u32(const void* p) {
    uint32_t a;
    asm("{ .reg .u64 t; cvta.to.shared.u64 t, %1; cvt.u32.u64 %0, t; }" : "=r"(a) : "l"(p));
    return a;
}
#define SWZ128(b) ((b) ^ (((b) >> 3) & 0x70))

__device__ __forceinline__ void cp16(uint32_t dst, const void* src, int src_sz) {
    asm volatile("cp.async.cg.shared.global [%0], [%1], 16, %2;"
                 :: "r"(dst), "l"(src), "r"(src_sz) : "memory");
}
__device__ __forceinline__ void cp_commit() {
    asm volatile("cp.async.commit_group;" ::: "memory");
}
template <int N>
__device__ __forceinline__ void cp_wait() {
    asm volatile("cp.async.wait_group %0;" :: "n"(N) : "memory");
}
__device__ __forceinline__ void ldsm4(uint32_t* r, uint32_t addr) {
    asm volatile("ldmatrix.sync.aligned.m8n8.x4.shared.b16 {%0,%1,%2,%3}, [%4];"
                 : "=r"(r[0]), "=r"(r[1]), "=r"(r[2]), "=r"(r[3]) : "r"(addr));
}
__device__ __forceinline__ void mma_f16(float* d, const uint32_t* a,
                                        uint32_t b0, uint32_t b1) {
    asm volatile(
        "mma.sync.aligned.m16n8k16.row.col.f32.f16.f16.f32 "
        "{%0,%1,%2,%3}, {%4,%5,%6,%7}, {%8,%9}, {%0,%1,%2,%3};"
        : "+f"(d[0]), "+f"(d[1]), "+f"(d[2]), "+f"(d[3])
        : "r"(a[0]), "r"(a[1]), "r"(a[2]), "r"(a[3]), "r"(b0), "r"(b1));
}

// ================= routing kernels =================
__global__ void init_kernel() {
    int t = threadIdx.x;
    if (t < N_EXPERTS) { g_count[t] = 0; g_cursor[t] = 0; }
}

__global__ void gate_kernel(const float* __restrict__ x,
                            const float* __restrict__ gw,
                            const float* __restrict__ gb) {
    int warp = (blockIdx.x * blockDim.x + threadIdx.x) >> 5;
    int lane = threadIdx.x & 31;
    if (warp >= N_TOKENS) return;
    const float* xr = x + (size_t)warp * D_MODEL;
    float acc[N_EXPERTS];
#pragma unroll
    for (int e = 0; e < N_EXPERTS; e++) acc[e] = 0.0f;
    for (int d = lane; d < D_MODEL; d += 32) {
        float xv = xr[d];
        const float* g = gw + (size_t)d * N_EXPERTS;
#pragma unroll
        for (int e = 0; e < N_EXPERTS; e++) acc[e] += xv * g[e];
    }
#pragma unroll
    for (int e = 0; e < N_EXPERTS; e++)
#pragma unroll
        for (int o = 16; o > 0; o >>= 1)
            acc[e] += __shfl_down_sync(0xffffffffu, acc[e], o);
    if (lane == 0) {
        int best = 0;
        float bv = acc[0] + gb[0];
#pragma unroll
        for (int e = 1; e < N_EXPERTS; e++) {
            float v = acc[e] + gb[e];
            if (v > bv) { bv = v; best = e; }
        }
        g_top1[warp] = best;
        atomicAdd(&g_count[best], 1);
    }
}

__global__ void scan_kernel() {
    int off = 0;
    for (int e = 0; e < N_EXPERTS; e++) { g_offset[e] = off; off += g_count[e]; }
}

__global__ void scatter_kernel() {
    int n = blockIdx.x * blockDim.x + threadIdx.x;
    if (n >= N_TOKENS) return;
    int e = g_top1[n];
    int pos = g_offset[e] + atomicAdd(&g_cursor[e], 1);
    g_perm[pos] = n;
}

// ================= conversion pre-passes =================
__global__ void convert_x_kernel(const float* __restrict__ x) {
    size_t i = (size_t)blockIdx.x * blockDim.x + threadIdx.x;  // float4 index
    float4 v = ((const float4*)x)[i];
    __half2 h0 = __floats2half2_rn(v.x, v.y);
    __half2 h1 = __floats2half2_rn(v.z, v.w);
    uint2 p;
    p.x = *(uint32_t*)&h0; p.y = *(uint32_t*)&h1;
    ((uint2*)g_xh)[i] = p;
}

// transpose W[e][k][f] -> W_t[e][f][k], 64x64 tiles
__global__ __launch_bounds__(256) void convert_w_kernel(const float* __restrict__ ew) {
    __shared__ float t[64][65];
    const int e = blockIdx.z;
    const int k0 = blockIdx.y * 64;
    const int f0 = blockIdx.x * 64;
    const float* W = ew + (size_t)e * D_MODEL * D_FF;
    const int tid = threadIdx.x;
#pragma unroll
    for (int p = 0; p < 16; p++) {
        int idx = p * 256 + tid;
        int r = idx >> 6, c = idx & 63;
        t[r][c] = W[(size_t)(k0 + r) * D_FF + f0 + c];
    }
    __syncthreads();
#pragma unroll
    for (int p = 0; p < 8; p++) {
        int idx = p * 256 + tid;
        int fr = idx >> 5, kc = (idx & 31) * 2;
        __half2 h = __floats2half2_rn(t[kc][fr], t[kc + 1][fr]);
        size_t o = ((size_t)e * D_FF + f0 + fr) * D_MODEL + k0 + kc;
        *(uint32_t*)(g_wh + o) = *(uint32_t*)&h;
    }
}

// ================= single-pass fp16 mma.sync grouped GEMM =================
// CTA: 128 threads (4 warps, 2x2), tile M=128 x N=128, warp tile 64x64.
// K chunks of 64 fp16 (one 128B SW128 row), 3-stage cp.async pipeline.
// R16 delta vs R10: single barrier per chunk; loads for c+2 issued BEFORE
// compute(c) so they overlap with a full compute phase.
#define KC 64
#define NCHUNK (D_MODEL / KC)        // 16
#define MATB 16384                   // 128 rows * 128B
#define BUFB (2 * MATB)              // A, B
#define STAGES 3
#define SMEM_DYN (STAGES * BUFB)     // 96 KB

__global__ __launch_bounds__(128, 2)
void moe_hmma_kernel(const float* __restrict__ eb, float* __restrict__ out) {
    extern __shared__ char smem[];
    __shared__ int rows_s[128];

    const int e = blockIdx.z;
    const int cnt = g_count[e];
    const int row0 = blockIdx.y * 128;
    if (row0 >= cnt) return;
    const int col0 = blockIdx.x * 128;
    const int off = g_offset[e];

    const int tid = threadIdx.x;
    const int wid = tid >> 5;
    const int lane = tid & 31;
    const uint32_t sdyn = smem_u32(smem);

    {
        int r = row0 + tid;
        rows_s[tid] = (r < cnt) ? g_perm[off + r] : -1;
    }
    __syncthreads();

    const uint32_t wbase = ((uint32_t)e * D_FF + (uint32_t)col0) * D_MODEL;

    // cp.async: 8 (row, seg) pairs per thread per matrix (as in R10)
#define ISSUE(cc)                                                           \
    {                                                                       \
        const uint32_t b0_ = sdyn + ((cc) % STAGES) * BUFB;                 \
        const uint32_t ke_ = (uint32_t)(cc) * KC;                           \
        _Pragma("unroll")                                                   \
        for (int p = 0; p < 8; p++) {                                       \
            const int idx = p * 128 + tid;                                  \
            const int r = idx >> 3, seg = idx & 7;                          \
            const uint32_t d = SWZ128((uint32_t)(r * 128 + seg * 16));      \
            const int tok = rows_s[r];                                      \
            cp16(b0_ + d,                                                   \
                 g_xh + ((size_t)(tok < 0 ? 0 : tok) * D_MODEL + seg * 8 + ke_), \
                 tok < 0 ? 0 : 16);                                         \
            cp16(b0_ + MATB + d,                                            \
                 g_wh + ((size_t)wbase + (uint32_t)r * D_MODEL + seg * 8 + ke_), \
                 16);                                                       \
        }                                                                   \
        cp_commit();                                                        \
    }

    // ---------- warp tiling: 2 (M) x 2 (N) warps, each 64x64 ---------------
    const int wm = wid & 1;
    const int wn = wid >> 1;
    const int mi = lane >> 3, r8 = lane & 7;
    const int am = (mi & 1) * 8 + r8;          // A: j&1 -> m+8, j>>1 -> k+8
    const int ak = (mi >> 1) * 8;
    const int bn = (mi >> 1) * 8 + r8;         // B: j>>1 -> n+8, j&1 -> k+8
    const int bk = (mi & 1) * 8;

    uint32_t a_rowb[4], a_msk[4];              // 4 m16 tiles
#pragma unroll
    for (int mt = 0; mt < 4; mt++) {
        int m = wm * 64 + mt * 16 + am;
        a_rowb[mt] = (uint32_t)m * 128;
        a_msk[mt]  = (uint32_t)(m & 7) << 4;
    }
    uint32_t b_rowb[4], b_msk[4];              // 4 n16 ldmatrix groups
#pragma unroll
    for (int q = 0; q < 4; q++) {
        int n = wn * 64 + q * 16 + bn;
        b_rowb[q] = (uint32_t)n * 128;
        b_msk[q]  = (uint32_t)(n & 7) << 4;
    }

    float acc[4][8][4];
#pragma unroll
    for (int i = 0; i < 4; i++)
#pragma unroll
        for (int j = 0; j < 8; j++)
#pragma unroll
            for (int k = 0; k < 4; k++) acc[i][j][k] = 0.0f;

    ISSUE(0); ISSUE(1);

    for (int c = 0; c < NCHUNK; c++) {
        cp_wait<1>();
        __syncthreads();
        // issue loads for chunk c+2 into stage (c+2)%3 == (c-1)%3, whose
        // consumer (compute c-1) finished before this barrier.
        if (c + 2 < NCHUNK) { ISSUE(c + 2); } else { cp_commit(); }

        const uint32_t Ab = sdyn + (c % STAGES) * BUFB;
        const uint32_t Bb = Ab + MATB;

#pragma unroll
        for (int ks = 0; ks < 4; ks++) {
            uint32_t af[4][4], bf[4][4];
            const uint32_t akb = (uint32_t)(ks * 32 + ak * 2);
            const uint32_t bkb = (uint32_t)(ks * 32 + bk * 2);
#pragma unroll
            for (int mt = 0; mt < 4; mt++)
                ldsm4(af[mt], Ab + a_rowb[mt] + (akb ^ a_msk[mt]));
#pragma unroll
            for (int q = 0; q < 4; q++)
                ldsm4(bf[q], Bb + b_rowb[q] + (bkb ^ b_msk[q]));
#pragma unroll
            for (int mt = 0; mt < 4; mt++)
#pragma unroll
                for (int nt = 0; nt < 8; nt++) {
                    const int q = nt >> 1, s = (nt & 1) * 2;
                    mma_f16(acc[mt][nt], af[mt], bf[q][s], bf[q][s + 1]);
                }
        }
    }
#undef ISSUE

    // ---------- epilogue: bias + scatter to token rows ---------------------
    const int l4 = lane >> 2;
    const int l2 = (lane & 3) * 2;
#pragma unroll
    for (int nt = 0; nt < 8; nt++) {
        const int col = col0 + wn * 64 + nt * 8 + l2;
        const float2 bv = *(const float2*)(eb + (size_t)e * D_FF + col);
#pragma unroll
        for (int mt = 0; mt < 4; mt++) {
            const int mA = wm * 64 + mt * 16 + l4;
            const int tokA = rows_s[mA];
            const int tokB = rows_s[mA + 8];
            if (tokA >= 0) {
                float2 v;
                v.x = acc[mt][nt][0] + bv.x;
                v.y = acc[mt][nt][1] + bv.y;
                *(float2*)(out + (size_t)tokA * D_FF + col) = v;
            }
            if (tokB >= 0) {
                float2 v;
                v.x = acc[mt][nt][2] + bv.x;
                v.y = acc[mt][nt][3] + bv.y;
                *(float2*)(out + (size_t)tokB * D_FF + col) = v;
            }
        }
    }
}

// ================= launch =================
extern "C" void kernel_launch(void* const* d_in, const int* in_sizes, int n_in,
                              void* d_out, int out_size) {
    const float* x  = (const float*)d_in[0];
    const float* gw = (const float*)d_in[1];
    const float* gb = (const float*)d_in[2];
    const float* ew = (const float*)d_in[3];
    const float* eb = (const float*)d_in[4];
    float* out = (float*)d_out;

    cudaFuncSetAttribute(moe_hmma_kernel, cudaFuncAttributeMaxDynamicSharedMemorySize, SMEM_DYN);

    init_kernel<<<1, 32>>>();
    gate_kernel<<<(N_TOKENS * 32 + 255) / 256, 256>>>(x, gw, gb);
    scan_kernel<<<1, 1>>>();
    scatter_kernel<<<(N_TOKENS + 255) / 256, 256>>>();

    convert_x_kernel<<<(N_TOKENS * D_MODEL / 4) / 256, 256>>>(x);
    dim3 wgrid(D_FF / 64, D_MODEL / 64, N_EXPERTS);
    convert_w_kernel<<<wgrid, 256>>>(ew);

    // x = N-tile fastest so concurrent CTAs share the A slab in L2
    dim3 grid(D_FF / 128, (N_TOKENS + 127) / 128, N_EXPERTS);
    moe_hmma_kernel<<<grid, 128, SMEM_DYN>>>(eb, out);
}